// round 1
// baseline (speedup 1.0000x reference)
#include <cuda_runtime.h>
#include <cstdint>
#include <cstddef>

#define Nn 100000
#define Ee 500000
#define Dd 128
#define Ll 5

// -------- scratch (device globals: allocation-free) --------
__device__ __align__(16) float g_h[(size_t)Nn * 128];
__device__ __align__(16) float g_agg[(size_t)Nn * 128];
__device__ __align__(16) float g_t1[(size_t)Nn * 256];
__device__ __align__(16) float g_t2[(size_t)Nn * 128];
__device__ float g_stats1[512];   // 256 sums, 256 sumsq
__device__ float g_stats2[256];   // 128 sums, 128 sumsq
__device__ float g_sc1[512];      // 256 scale, 256 shift
__device__ float g_sc2[256];      // 128 scale, 128 shift

// -------- h init: h[n,d] = sum_f atom_emb[f, x[n,f], d] --------
__global__ void init_h_kernel(const int* __restrict__ x,
                              const float* __restrict__ ae,
                              float* __restrict__ h) {
    int idx = blockIdx.x * blockDim.x + threadIdx.x;
    if (idx >= Nn * 128) return;
    int n = idx >> 7, d = idx & 127;
    float s = 0.f;
#pragma unroll
    for (int f = 0; f < 9; f++) {
        int xi = __ldg(x + n * 9 + f);
        s += __ldg(ae + (((size_t)(f * 120 + xi)) << 7) + d);
    }
    h[idx] = s;
}

// -------- edge kernel: agg[dst] += relu(h[src] + bond_e) * ew --------
__global__ void __launch_bounds__(256) edge_kernel(
    const float* __restrict__ h, const float* __restrict__ be,
    const int* __restrict__ ei, const int* __restrict__ ea,
    const float* __restrict__ ew, float* __restrict__ agg)
{
    __shared__ __align__(16) float sbe[3 * 8 * 128];   // bond_emb for this layer (12KB)
    for (int i = threadIdx.x; i < 3 * 8 * 128; i += 256) sbe[i] = be[i];
    __syncthreads();

    int gwarp = (blockIdx.x * 256 + threadIdx.x) >> 5;
    int lane  = threadIdx.x & 31;
    int nw    = (gridDim.x * 256) >> 5;
    int d0    = lane * 4;

    for (int e = gwarp; e < Ee; e += nw) {
        int src = __ldg(ei + e);
        int dst = __ldg(ei + Ee + e);
        int a0  = __ldg(ea + e * 3 + 0);
        int a1  = __ldg(ea + e * 3 + 1);
        int a2  = __ldg(ea + e * 3 + 2);
        float w = __ldg(ew + e);

        const float4 hv = *(const float4*)(h + (size_t)src * 128 + d0);
        const float4 e0 = *(const float4*)(sbe + (a0      ) * 128 + d0);
        const float4 e1 = *(const float4*)(sbe + (8  + a1 ) * 128 + d0);
        const float4 e2 = *(const float4*)(sbe + (16 + a2 ) * 128 + d0);

        float m0 = fmaxf(hv.x + e0.x + e1.x + e2.x, 0.f) * w;
        float m1 = fmaxf(hv.y + e0.y + e1.y + e2.y, 0.f) * w;
        float m2 = fmaxf(hv.z + e0.z + e1.z + e2.z, 0.f) * w;
        float m3 = fmaxf(hv.w + e0.w + e1.w + e2.w, 0.f) * w;

        float* p = agg + (size_t)dst * 128 + d0;
        asm volatile("red.global.add.v4.f32 [%0], {%1,%2,%3,%4};"
                     :: "l"(p), "f"(m0), "f"(m1), "f"(m2), "f"(m3) : "memory");
    }
}

// -------- GEMM: C[M,NC] = X @ W + bias, + per-column sum/sumsq stats --------
// MODE 0: X = (1+eps[layer])*A + A2            (z build fused; K=128, NC=256)
// MODE 1: X = relu(sc[k]*A + sh[k])            (BN1+ReLU fused; K=256, NC=128)
template <int MODE>
__global__ void __launch_bounds__(256) gemm_kernel(
    const float* __restrict__ A, const float* __restrict__ A2,
    const float* __restrict__ epsp, int layer,
    const float* __restrict__ scsh,
    const float* __restrict__ W, const float* __restrict__ bias,
    float* __restrict__ C, float* __restrict__ stats,
    int M, int K, int NC)
{
    __shared__ __align__(16) float As[16][132];
    __shared__ __align__(16) float Ws[16][128];
    __shared__ float s_sum[128];
    __shared__ float s_sq[128];

    const int tid = threadIdx.x;
    const int tx = tid & 15, ty = tid >> 4;
    const int rowBase = blockIdx.x * 128;
    const int colBase = blockIdx.y * 128;

    float alpha = 1.0f;
    if (MODE == 0) alpha = 1.0f + __ldg(epsp + layer);
    const float* shv = (MODE == 1) ? (scsh + K) : (const float*)nullptr;

    float acc[8][8];
#pragma unroll
    for (int i = 0; i < 8; i++)
#pragma unroll
        for (int j = 0; j < 8; j++) acc[i][j] = 0.f;

    for (int k0 = 0; k0 < K; k0 += 16) {
        // ---- A tile (transposed into shared), with fused transform ----
#pragma unroll
        for (int ld = 0; ld < 2; ld++) {
            int t  = tid + ld * 256;
            int r  = t >> 2;           // 0..127
            int kq = (t & 3) * 4;      // 0,4,8,12
            int rg = rowBase + r;
            float4 v = make_float4(0.f, 0.f, 0.f, 0.f);
            if (rg < M) {
                const float4 av = *(const float4*)(A + (size_t)rg * K + k0 + kq);
                if (MODE == 0) {
                    const float4 gv = *(const float4*)(A2 + (size_t)rg * K + k0 + kq);
                    v.x = fmaf(alpha, av.x, gv.x);
                    v.y = fmaf(alpha, av.y, gv.y);
                    v.z = fmaf(alpha, av.z, gv.z);
                    v.w = fmaf(alpha, av.w, gv.w);
                } else {
                    int kg = k0 + kq;
                    v.x = fmaxf(fmaf(__ldg(scsh + kg + 0), av.x, __ldg(shv + kg + 0)), 0.f);
                    v.y = fmaxf(fmaf(__ldg(scsh + kg + 1), av.y, __ldg(shv + kg + 1)), 0.f);
                    v.z = fmaxf(fmaf(__ldg(scsh + kg + 2), av.z, __ldg(shv + kg + 2)), 0.f);
                    v.w = fmaxf(fmaf(__ldg(scsh + kg + 3), av.w, __ldg(shv + kg + 3)), 0.f);
                }
            }
            As[kq + 0][r] = v.x;
            As[kq + 1][r] = v.y;
            As[kq + 2][r] = v.z;
            As[kq + 3][r] = v.w;
        }
        // ---- W tile ----
#pragma unroll
        for (int ld = 0; ld < 2; ld++) {
            int t  = tid + ld * 256;
            int kr = t >> 5;           // 0..15
            int c4 = (t & 31) * 4;     // 0..124
            *(float4*)&Ws[kr][c4] =
                *(const float4*)(W + (size_t)(k0 + kr) * NC + colBase + c4);
        }
        __syncthreads();

#pragma unroll
        for (int kk = 0; kk < 16; kk++) {
            float4 a0 = *(const float4*)&As[kk][ty * 8];
            float4 a1 = *(const float4*)&As[kk][ty * 8 + 4];
            float4 b0 = *(const float4*)&Ws[kk][tx * 8];
            float4 b1 = *(const float4*)&Ws[kk][tx * 8 + 4];
            float a[8] = {a0.x, a0.y, a0.z, a0.w, a1.x, a1.y, a1.z, a1.w};
            float b[8] = {b0.x, b0.y, b0.z, b0.w, b1.x, b1.y, b1.z, b1.w};
#pragma unroll
            for (int i = 0; i < 8; i++)
#pragma unroll
                for (int j = 0; j < 8; j++)
                    acc[i][j] = fmaf(a[i], b[j], acc[i][j]);
        }
        __syncthreads();
    }

    // ---- epilogue: bias, store, column stats ----
    float bv[8];
#pragma unroll
    for (int j = 0; j < 8; j++) bv[j] = __ldg(bias + colBase + tx * 8 + j);
#pragma unroll
    for (int i = 0; i < 8; i++)
#pragma unroll
        for (int j = 0; j < 8; j++) acc[i][j] += bv[j];

    if (tid < 128) { s_sum[tid] = 0.f; s_sq[tid] = 0.f; }
    __syncthreads();

#pragma unroll
    for (int j = 0; j < 8; j++) {
        float cs = 0.f, cq = 0.f;
#pragma unroll
        for (int i = 0; i < 8; i++) {
            int rg = rowBase + ty * 8 + i;
            if (rg < M) { float v = acc[i][j]; cs += v; cq += v * v; }
        }
        atomicAdd(&s_sum[tx * 8 + j], cs);
        atomicAdd(&s_sq[tx * 8 + j], cq);
    }

#pragma unroll
    for (int i = 0; i < 8; i++) {
        int rg = rowBase + ty * 8 + i;
        if (rg < M) {
            float4 o0 = make_float4(acc[i][0], acc[i][1], acc[i][2], acc[i][3]);
            float4 o1 = make_float4(acc[i][4], acc[i][5], acc[i][6], acc[i][7]);
            *(float4*)(C + (size_t)rg * NC + colBase + tx * 8)     = o0;
            *(float4*)(C + (size_t)rg * NC + colBase + tx * 8 + 4) = o1;
        }
    }
    __syncthreads();
    if (tid < 128) {
        atomicAdd(&stats[colBase + tid],      s_sum[tid]);
        atomicAdd(&stats[NC + colBase + tid], s_sq[tid]);
    }
}

// -------- BN finalize: scale/shift from sums --------
__global__ void finalize_bn(const float* __restrict__ stats,
                            const float* __restrict__ g,
                            const float* __restrict__ bt,
                            float* __restrict__ scsh, int Cc) {
    int c = blockIdx.x * blockDim.x + threadIdx.x;
    if (c >= Cc) return;
    const float inv = 1.0f / (float)Nn;
    float mu  = stats[c] * inv;
    float var = stats[Cc + c] * inv - mu * mu;
    float sc  = __ldg(g + c) * rsqrtf(var + 1e-5f);
    scsh[c]      = sc;
    scsh[Cc + c] = fmaf(-mu, sc, __ldg(bt + c));
}

// -------- apply BN2 (+optional relu) --------
__global__ void apply_bn(const float* __restrict__ t2,
                         const float* __restrict__ scsh,
                         float* __restrict__ outp, int do_relu) {
    int idx = blockIdx.x * blockDim.x + threadIdx.x;
    if (idx >= Nn * 128) return;
    int c = idx & 127;
    float v = fmaf(scsh[c], t2[idx], scsh[128 + c]);
    outp[idx] = do_relu ? fmaxf(v, 0.f) : v;
}

extern "C" void kernel_launch(void* const* d_in, const int* in_sizes, int n_in,
                              void* d_out, int out_size) {
    const int*   x    = (const int*)d_in[0];
    const int*   ei   = (const int*)d_in[1];
    const int*   ea   = (const int*)d_in[2];
    const float* ew   = (const float*)d_in[3];
    const float* ae   = (const float*)d_in[4];
    const float* be   = (const float*)d_in[5];
    const float* eps  = (const float*)d_in[6];
    const float* W1   = (const float*)d_in[7];
    const float* b1   = (const float*)d_in[8];
    const float* g1   = (const float*)d_in[9];
    const float* bt1  = (const float*)d_in[10];
    const float* W2   = (const float*)d_in[11];
    const float* b2   = (const float*)d_in[12];
    const float* go   = (const float*)d_in[13];
    const float* bto  = (const float*)d_in[14];
    float* out = (float*)d_out;

    float *h, *agg, *t1, *t2, *st1, *st2, *sc1, *sc2;
    cudaGetSymbolAddress((void**)&h,   g_h);
    cudaGetSymbolAddress((void**)&agg, g_agg);
    cudaGetSymbolAddress((void**)&t1,  g_t1);
    cudaGetSymbolAddress((void**)&t2,  g_t2);
    cudaGetSymbolAddress((void**)&st1, g_stats1);
    cudaGetSymbolAddress((void**)&st2, g_stats2);
    cudaGetSymbolAddress((void**)&sc1, g_sc1);
    cudaGetSymbolAddress((void**)&sc2, g_sc2);

    const int elem_blocks = (Nn * 128 + 255) / 256;
    init_h_kernel<<<elem_blocks, 256>>>(x, ae, h);

    for (int l = 0; l < Ll; l++) {
        cudaMemsetAsync(agg, 0, (size_t)Nn * 128 * sizeof(float));
        cudaMemsetAsync(st1, 0, 512 * sizeof(float));
        cudaMemsetAsync(st2, 0, 256 * sizeof(float));

        edge_kernel<<<2048, 256>>>(h, be + (size_t)l * 3 * 8 * 128, ei, ea, ew, agg);

        dim3 grid1((Nn + 127) / 128, 2);
        gemm_kernel<0><<<grid1, 256>>>(h, agg, eps, l, (const float*)nullptr,
                                       W1 + (size_t)l * 128 * 256, b1 + l * 256,
                                       t1, st1, Nn, 128, 256);
        finalize_bn<<<1, 256>>>(st1, g1 + l * 256, bt1 + l * 256, sc1, 256);

        dim3 grid2((Nn + 127) / 128, 1);
        gemm_kernel<1><<<grid2, 256>>>(t1, (const float*)nullptr,
                                       (const float*)nullptr, 0, sc1,
                                       W2 + (size_t)l * 256 * 128, b2 + l * 128,
                                       t2, st2, Nn, 256, 128);
        finalize_bn<<<1, 128>>>(st2, go + l * 128, bto + l * 128, sc2, 128);

        float* dsth = (l == Ll - 1) ? out : h;
        apply_bn<<<elem_blocks, 256>>>(t2, sc2, dsth, (l < Ll - 1) ? 1 : 0);
    }
}